// round 1
// baseline (speedup 1.0000x reference)
#include <cuda_runtime.h>
#include <math.h>

#define D        64
#define N_USERS  100000
#define N_ITEMS  50000
#define N_ENT    180000
#define N_UN     150000

// ---- scratch (no allocations allowed) ----
__device__ float g_iu[(size_t)N_ITEMS * D];   // i_u_agg raw sums
__device__ float g_ui[(size_t)N_USERS * D];   // u_i_agg raw sums
__device__ float g_cnt_e[N_ENT];
__device__ float g_cnt_u[N_UN];
__device__ float g_cnt_iu[N_ITEMS];
__device__ float g_cnt_ui[N_USERS];

// ---------------- zero everything we accumulate into ----------------
__global__ void zero_all(float4* out, long n_out4,
                         float4* iu, long n_iu4,
                         float4* ui, long n_ui4,
                         float4* ce, long n_ce4,
                         float4* cu, long n_cu4,
                         float4* ciu, long n_ciu4,
                         float4* cui, long n_cui4)
{
    long i = (long)blockIdx.x * blockDim.x + threadIdx.x;
    long stride = (long)gridDim.x * blockDim.x;
    float4 z = make_float4(0.f, 0.f, 0.f, 0.f);
    for (long k = i; k < n_out4; k += stride) out[k] = z;
    for (long k = i; k < n_iu4;  k += stride) iu[k]  = z;
    for (long k = i; k < n_ui4;  k += stride) ui[k]  = z;
    for (long k = i; k < n_ce4;  k += stride) ce[k]  = z;
    for (long k = i; k < n_cu4;  k += stride) cu[k]  = z;
    for (long k = i; k < n_ciu4; k += stride) ciu[k] = z;
    for (long k = i; k < n_cui4; k += stride) cui[k] = z;
}

// ---------------- scatter-add: dst[d] += emb[s] * weight[type] ----------------
// 16 threads per edge, float4 per thread, vector red to L2.
__global__ __launch_bounds__(256) void scatter_kernel(
    const float* __restrict__ src_emb,
    const float* __restrict__ weight,
    const int*   __restrict__ src_idx,
    const int*   __restrict__ dst_idx,
    const int*   __restrict__ etype,   // nullptr => weight row 0
    float*       __restrict__ dst,
    float*       __restrict__ cnt,
    int nedges)
{
    int gid  = blockIdx.x * blockDim.x + threadIdx.x;
    int e    = gid >> 4;
    int lane = gid & 15;
    if (e >= nedges) return;

    int s = src_idx[e];
    int d = dst_idx[e];
    int t = etype ? etype[e] : 0;

    const float4* sr = (const float4*)(src_emb + (size_t)s * D);
    const float4* wr = (const float4*)(weight  + (size_t)t * D);
    float4 v = sr[lane];
    float4 w = wr[lane];
    float4 r = make_float4(v.x * w.x, v.y * w.y, v.z * w.z, v.w * w.w);

    float* p = dst + (size_t)d * D + lane * 4;
    asm volatile("red.global.add.v4.f32 [%0], {%1,%2,%3,%4};"
                 :: "l"(p), "f"(r.x), "f"(r.y), "f"(r.z), "f"(r.w) : "memory");
    if (lane == 0) atomicAdd(cnt + d, 1.0f);
}

// ---------------- divide rows [row0,row1) by clipped count (in place) --------
__global__ void divide_kernel(float* base, const float* __restrict__ cnt,
                              int row0, int row1)
{
    int gid = blockIdx.x * blockDim.x + threadIdx.x;
    int n = (row1 - row0) * 16;
    if (gid >= n) return;
    int r = row0 + (gid >> 4);
    int lane = gid & 15;
    float c = fmaxf(cnt[r], 1.0f);
    float inv = 1.0f / c;
    float4* p = (float4*)(base + (size_t)r * D) + lane;
    float4 v = *p;
    v.x *= inv; v.y *= inv; v.z *= inv; v.w *= inv;
    *p = v;
}

// ---------------- gated fusion:
// out = sig(Am @ Ga^T + Bm @ Gb^T) * Am + (1 - sig) * Bm
// where Am = A/clip(cntA), Bm = B/clip(cntB); A rows come from `out` base (raw
// sums) and are overwritten with the fused result.
__global__ __launch_bounds__(256) void fusion_kernel(
    const float* __restrict__ A, const float* __restrict__ cntA,
    const float* __restrict__ B, const float* __restrict__ cntB,
    const float* __restrict__ Ga, const float* __restrict__ Gb,
    float* __restrict__ out, int nrows)
{
    __shared__ float sGa[64 * 65];
    __shared__ float sGb[64 * 65];
    __shared__ float sA[16][64];
    __shared__ float sB[16][64];

    int t = threadIdx.x;
    // load gates transposed: sG[k*65 + j] = G[j*64 + k] (conflict-free both ways)
    for (int idx = t; idx < 4096; idx += 256) {
        int j = idx >> 6, k = idx & 63;
        sGa[k * 65 + j] = Ga[idx];
        sGb[k * 65 + j] = Gb[idx];
    }
    __syncthreads();

    int ntiles = (nrows + 15) >> 4;
    for (int tile = blockIdx.x; tile < ntiles; tile += gridDim.x) {
        int row0 = tile << 4;
        // stage 16 rows of A and B, pre-divided by counts
        for (int idx = t; idx < 1024; idx += 256) {
            int r = idx >> 6, k = idx & 63;
            int row = row0 + r;
            float a = 0.f, b = 0.f;
            if (row < nrows) {
                float ia = 1.0f / fmaxf(cntA[row], 1.0f);
                float ib = 1.0f / fmaxf(cntB[row], 1.0f);
                a = A[(size_t)row * D + k] * ia;
                b = B[(size_t)row * D + k] * ib;
            }
            sA[r][k] = a;
            sB[r][k] = b;
        }
        __syncthreads();

        // each thread: rows (r0, r0+8) x cols (j0, j0+32)
        int j0 = t & 31;
        int r0 = t >> 5;
        float aa00 = 0.f, aa01 = 0.f, aa10 = 0.f, aa11 = 0.f;
        float bb00 = 0.f, bb01 = 0.f, bb10 = 0.f, bb11 = 0.f;
        #pragma unroll
        for (int k = 0; k < 64; k++) {
            float ga0 = sGa[k * 65 + j0];
            float ga1 = sGa[k * 65 + j0 + 32];
            float gb0 = sGb[k * 65 + j0];
            float gb1 = sGb[k * 65 + j0 + 32];
            float a0 = sA[r0][k],     a1 = sA[r0 + 8][k];
            float b0 = sB[r0][k],     b1 = sB[r0 + 8][k];
            aa00 += a0 * ga0; aa01 += a0 * ga1;
            aa10 += a1 * ga0; aa11 += a1 * ga1;
            bb00 += b0 * gb0; bb01 += b0 * gb1;
            bb10 += b1 * gb0; bb11 += b1 * gb1;
        }

        #pragma unroll
        for (int q = 0; q < 4; q++) {
            int rr = r0 + ((q >> 1) ? 8 : 0);
            int jj = j0 + ((q & 1) ? 32 : 0);
            float x;
            if (q == 0) x = aa00 + bb00;
            else if (q == 1) x = aa01 + bb01;
            else if (q == 2) x = aa10 + bb10;
            else x = aa11 + bb11;
            int row = row0 + rr;
            if (row < nrows) {
                float g = 1.0f / (1.0f + __expf(-x));
                float aval = sA[rr][jj];
                float bval = sB[rr][jj];
                out[(size_t)row * D + jj] = g * aval + (1.0f - g) * bval;
            }
        }
        __syncthreads();
    }
}

extern "C" void kernel_launch(void* const* d_in, const int* in_sizes, int n_in,
                              void* d_out, int out_size)
{
    const float* entity_emb = (const float*)d_in[0];
    const float* user_emb   = (const float*)d_in[1];
    const float* weight     = (const float*)d_in[2];
    const float* gate1_w    = (const float*)d_in[3];
    const float* gate2_w    = (const float*)d_in[4];
    const float* gate3_w    = (const float*)d_in[5];
    const int* edge_index       = (const int*)d_in[6];
    const int* edge_type        = (const int*)d_in[7];
    const int* user_edge_index  = (const int*)d_in[8];
    const int* user_edge_type   = (const int*)d_in[9];
    const int* mat_row          = (const int*)d_in[10];
    const int* mat_col          = (const int*)d_in[11];

    int E  = in_sizes[7];          // 1.5M KG edges
    int UE = in_sizes[9];          // 1.0M user edges
    int M  = in_sizes[10];         // 1.5M interaction edges

    float* out     = (float*)d_out;
    float* ent_out = out;                         // entity_agg accumulates here
    float* usr_out = out + (size_t)N_ENT * D;     // attribute_agg accumulates here

    float *p_iu, *p_ui, *p_ce, *p_cu, *p_ciu, *p_cui;
    cudaGetSymbolAddress((void**)&p_iu,  g_iu);
    cudaGetSymbolAddress((void**)&p_ui,  g_ui);
    cudaGetSymbolAddress((void**)&p_ce,  g_cnt_e);
    cudaGetSymbolAddress((void**)&p_cu,  g_cnt_u);
    cudaGetSymbolAddress((void**)&p_ciu, g_cnt_iu);
    cudaGetSymbolAddress((void**)&p_cui, g_cnt_ui);

    // 1) zero accumulators (d_out itself is an accumulator)
    zero_all<<<2048, 256>>>((float4*)out, (long)(N_ENT + N_UN) * D / 4,
                            (float4*)p_iu,  (long)N_ITEMS * D / 4,
                            (float4*)p_ui,  (long)N_USERS * D / 4,
                            (float4*)p_ce,  N_ENT / 4,
                            (float4*)p_cu,  N_UN / 4,
                            (float4*)p_ciu, N_ITEMS / 4,
                            (float4*)p_cui, N_USERS / 4);

    // 2) four scatter-adds
    {
        int blocks = (E * 16 + 255) / 256;
        scatter_kernel<<<blocks, 256>>>(entity_emb, weight,
                                        edge_index + E,  // tail (src)
                                        edge_index,      // head (dst)
                                        edge_type, ent_out, p_ce, E);
    }
    {
        int blocks = (UE * 16 + 255) / 256;
        scatter_kernel<<<blocks, 256>>>(user_emb, weight,
                                        user_edge_index + UE, // utail
                                        user_edge_index,      // uhead
                                        user_edge_type, usr_out, p_cu, UE);
    }
    {
        int blocks = (M * 16 + 255) / 256;
        // i_u_agg: user_emb[mat_row] * weight[0] scattered by mat_col
        scatter_kernel<<<blocks, 256>>>(user_emb, weight,
                                        mat_row, mat_col, nullptr,
                                        p_iu, p_ciu, M);
        // u_i_agg: entity_emb[mat_col] * weight[0] scattered by mat_row
        scatter_kernel<<<blocks, 256>>>(entity_emb, weight,
                                        mat_col, mat_row, nullptr,
                                        p_ui, p_cui, M);
    }

    // 3) divide tail regions (final output there is just scatter-mean)
    {
        int n = (N_ENT - N_ITEMS) * 16;
        divide_kernel<<<(n + 255) / 256, 256>>>(ent_out, p_ce, N_ITEMS, N_ENT);
    }
    {
        int n = (N_UN - N_USERS) * 16;
        divide_kernel<<<(n + 255) / 256, 256>>>(usr_out, p_cu, N_USERS, N_UN);
    }

    // 4) gated fusion (in place over first N_ITEMS / N_USERS rows)
    fusion_kernel<<<888, 256>>>(ent_out, p_ce, p_iu, p_ciu,
                                gate1_w, gate2_w, ent_out, N_ITEMS);
    fusion_kernel<<<888, 256>>>(usr_out, p_cu, p_ui, p_cui,
                                gate3_w, gate2_w, usr_out, N_USERS);
}

// round 2
// speedup vs baseline: 1.3134x; 1.3134x over previous
#include <cuda_runtime.h>
#include <math.h>

#define D        64
#define N_USERS  100000
#define N_ITEMS  50000
#define N_ENT    180000
#define N_UN     150000
#define E_KG     1500000
#define E_USR    1000000
#define E_MAT    1500000
#define EMASK    0xFFFFF

// ---------------- static scratch (no allocations allowed) ----------------
__device__ int g_cnt_e[N_ENT],   g_off_e[N_ENT];
__device__ int g_cnt_u[N_UN],    g_off_u[N_UN];
__device__ int g_cnt_ic[N_ITEMS],g_off_ic[N_ITEMS];   // mat_col histogram (items)
__device__ int g_cnt_ur[N_USERS],g_off_ur[N_USERS];   // mat_row histogram (users)
__device__ int g_cursor[4];
__device__ int g_rank_kg[E_KG], g_rank_u[E_USR], g_rank_mc[E_MAT], g_rank_mr[E_MAT];
__device__ int g_bkt_e[E_KG],   g_bkt_u[E_USR],  g_bkt_ic[E_MAT],  g_bkt_ur[E_MAT];
__device__ float g_iu[(size_t)N_ITEMS * D];   // i_u_agg (means)
__device__ float g_ui[(size_t)N_USERS * D];   // u_i_agg (means)

// ---------------- zero the histograms + cursors ----------------
__global__ void zero_counts(int* a, int na, int* b, int nb,
                            int* c, int nc, int* d, int nd, int* cur)
{
    int i = blockIdx.x * blockDim.x + threadIdx.x;
    int stride = gridDim.x * blockDim.x;
    for (int k = i; k < na; k += stride) a[k] = 0;
    for (int k = i; k < nb; k += stride) b[k] = 0;
    for (int k = i; k < nc; k += stride) c[k] = 0;
    for (int k = i; k < nd; k += stride) d[k] = 0;
    if (i < 4) cur[i] = 0;
}

// ---------------- histogram + per-edge rank ----------------
__global__ void hist_kernel(const int* __restrict__ dst_idx,
                            int* cnt, int* rank, int n)
{
    int e = blockIdx.x * blockDim.x + threadIdx.x;
    if (e < n) rank[e] = atomicAdd(cnt + dst_idx[e], 1);
}

__global__ void hist_mat_kernel(const int* __restrict__ mrow,
                                const int* __restrict__ mcol,
                                int* cnt_ur, int* rank_mr,
                                int* cnt_ic, int* rank_mc, int n)
{
    int e = blockIdx.x * blockDim.x + threadIdx.x;
    if (e < n) {
        rank_mr[e] = atomicAdd(cnt_ur + mrow[e], 1);
        rank_mc[e] = atomicAdd(cnt_ic + mcol[e], 1);
    }
}

// ---------------- offsets: block-aggregated exclusive scan ----------------
__global__ void offsets_kernel(const int* __restrict__ cnt, int* off,
                               int* cursor, int n)
{
    __shared__ int wsum[8];
    __shared__ int bbase;
    int i = blockIdx.x * 256 + threadIdx.x;
    int lane = threadIdx.x & 31, w = threadIdx.x >> 5;
    int v = (i < n) ? cnt[i] : 0;
    int x = v;
    #pragma unroll
    for (int d = 1; d < 32; d <<= 1) {
        int y = __shfl_up_sync(0xFFFFFFFFu, x, d);
        if (lane >= d) x += y;
    }
    if (lane == 31) wsum[w] = x;
    __syncthreads();
    if (threadIdx.x == 0) {
        int run = 0;
        #pragma unroll
        for (int k = 0; k < 8; k++) { int t = wsum[k]; wsum[k] = run; run += t; }
        bbase = atomicAdd(cursor, run);
    }
    __syncthreads();
    if (i < n) off[i] = bbase + wsum[w] + (x - v);
}

// ---------------- fill buckets (pure stores) ----------------
__global__ void fill_kernel(const int* __restrict__ dst_idx,
                            const int* __restrict__ src_idx,
                            const int* __restrict__ etype,
                            const int* __restrict__ off,
                            const int* __restrict__ rank,
                            int* bkt, int n)
{
    int e = blockIdx.x * blockDim.x + threadIdx.x;
    if (e >= n) return;
    int packed = src_idx[e] | (etype[e] << 20);
    bkt[off[dst_idx[e]] + rank[e]] = packed;
}

__global__ void fill_mat_kernel(const int* __restrict__ mrow,
                                const int* __restrict__ mcol,
                                const int* __restrict__ off_ur,
                                const int* __restrict__ rank_mr, int* bkt_ur,
                                const int* __restrict__ off_ic,
                                const int* __restrict__ rank_mc, int* bkt_ic,
                                int n)
{
    int e = blockIdx.x * blockDim.x + threadIdx.x;
    if (e >= n) return;
    int r = mrow[e], c = mcol[e];
    bkt_ur[off_ur[r] + rank_mr[e]] = c;   // for u_i: src = entity/item idx
    bkt_ic[off_ic[c] + rank_mc[e]] = r;   // for i_u: src = user idx
}

// ---------------- gather: one warp per destination row, write mean ----------
template<bool HT>
__global__ __launch_bounds__(256) void gather_kernel(
    const float* __restrict__ emb, const float* __restrict__ wgt,
    const int* __restrict__ bkt, const int* __restrict__ off,
    const int* __restrict__ cnt, float* __restrict__ out, int nrows)
{
    __shared__ float2 sW[32 * 32];
    if (HT) {
        for (int i = threadIdx.x; i < 1024; i += 256)
            sW[i] = ((const float2*)wgt)[i];
        __syncthreads();
    }
    int gid = blockIdx.x * 256 + threadIdx.x;
    int r = gid >> 5;
    int lane = gid & 31;
    if (r >= nrows) return;

    float2 w0;
    if (!HT) w0 = __ldg((const float2*)wgt + lane);

    int o = __ldg(off + r);
    int n = __ldg(cnt + r);
    float2 a0 = make_float2(0.f, 0.f), a1 = make_float2(0.f, 0.f);
    int j = 0;
    for (; j + 1 < n; j += 2) {
        int p0 = __ldg(bkt + o + j);
        int p1 = __ldg(bkt + o + j + 1);
        float2 v0 = __ldg((const float2*)(emb + ((size_t)(p0 & EMASK) << 6)) + lane);
        float2 v1 = __ldg((const float2*)(emb + ((size_t)(p1 & EMASK) << 6)) + lane);
        float2 wa = HT ? sW[(((unsigned)p0 >> 20) << 5) + lane] : w0;
        float2 wb = HT ? sW[(((unsigned)p1 >> 20) << 5) + lane] : w0;
        a0.x = fmaf(v0.x, wa.x, a0.x); a0.y = fmaf(v0.y, wa.y, a0.y);
        a1.x = fmaf(v1.x, wb.x, a1.x); a1.y = fmaf(v1.y, wb.y, a1.y);
    }
    if (j < n) {
        int p0 = __ldg(bkt + o + j);
        float2 v0 = __ldg((const float2*)(emb + ((size_t)(p0 & EMASK) << 6)) + lane);
        float2 wa = HT ? sW[(((unsigned)p0 >> 20) << 5) + lane] : w0;
        a0.x = fmaf(v0.x, wa.x, a0.x); a0.y = fmaf(v0.y, wa.y, a0.y);
    }
    float inv = 1.f / fmaxf((float)n, 1.f);
    float2 res = make_float2((a0.x + a1.x) * inv, (a0.y + a1.y) * inv);
    *((float2*)(out + ((size_t)r << 6)) + lane) = res;
}

// ---------------- gated fusion (inputs are means) ----------------
// out = sig(A @ Ga^T + B @ Gb^T) * A + (1 - sig) * B    (in place over A rows)
__global__ __launch_bounds__(256) void fusion_kernel(
    const float* __restrict__ A, const float* __restrict__ B,
    const float* __restrict__ Ga, const float* __restrict__ Gb,
    float* __restrict__ out, int nrows)
{
    __shared__ float sGa[64 * 65];
    __shared__ float sGb[64 * 65];
    __shared__ float sA[16][64];
    __shared__ float sB[16][64];

    int t = threadIdx.x;
    for (int idx = t; idx < 4096; idx += 256) {
        int j = idx >> 6, k = idx & 63;
        sGa[k * 65 + j] = Ga[idx];
        sGb[k * 65 + j] = Gb[idx];
    }
    __syncthreads();

    int ntiles = (nrows + 15) >> 4;
    for (int tile = blockIdx.x; tile < ntiles; tile += gridDim.x) {
        int row0 = tile << 4;
        for (int idx = t; idx < 1024; idx += 256) {
            int r = idx >> 6, k = idx & 63;
            int row = row0 + r;
            float a = 0.f, b = 0.f;
            if (row < nrows) {
                a = A[(size_t)row * D + k];
                b = B[(size_t)row * D + k];
            }
            sA[r][k] = a;
            sB[r][k] = b;
        }
        __syncthreads();

        int j0 = t & 31;
        int r0 = t >> 5;
        float aa00 = 0.f, aa01 = 0.f, aa10 = 0.f, aa11 = 0.f;
        float bb00 = 0.f, bb01 = 0.f, bb10 = 0.f, bb11 = 0.f;
        #pragma unroll
        for (int k = 0; k < 64; k++) {
            float ga0 = sGa[k * 65 + j0];
            float ga1 = sGa[k * 65 + j0 + 32];
            float gb0 = sGb[k * 65 + j0];
            float gb1 = sGb[k * 65 + j0 + 32];
            float a0 = sA[r0][k], a1 = sA[r0 + 8][k];
            float b0 = sB[r0][k], b1 = sB[r0 + 8][k];
            aa00 = fmaf(a0, ga0, aa00); aa01 = fmaf(a0, ga1, aa01);
            aa10 = fmaf(a1, ga0, aa10); aa11 = fmaf(a1, ga1, aa11);
            bb00 = fmaf(b0, gb0, bb00); bb01 = fmaf(b0, gb1, bb01);
            bb10 = fmaf(b1, gb0, bb10); bb11 = fmaf(b1, gb1, bb11);
        }

        #pragma unroll
        for (int q = 0; q < 4; q++) {
            int rr = r0 + ((q >> 1) ? 8 : 0);
            int jj = j0 + ((q & 1) ? 32 : 0);
            float x;
            if (q == 0) x = aa00 + bb00;
            else if (q == 1) x = aa01 + bb01;
            else if (q == 2) x = aa10 + bb10;
            else x = aa11 + bb11;
            int row = row0 + rr;
            if (row < nrows) {
                float g = 1.0f / (1.0f + __expf(-x));
                out[(size_t)row * D + jj] = g * sA[rr][jj] + (1.0f - g) * sB[rr][jj];
            }
        }
        __syncthreads();
    }
}

extern "C" void kernel_launch(void* const* d_in, const int* in_sizes, int n_in,
                              void* d_out, int out_size)
{
    const float* entity_emb = (const float*)d_in[0];
    const float* user_emb   = (const float*)d_in[1];
    const float* weight     = (const float*)d_in[2];
    const float* gate1_w    = (const float*)d_in[3];
    const float* gate2_w    = (const float*)d_in[4];
    const float* gate3_w    = (const float*)d_in[5];
    const int* edge_index      = (const int*)d_in[6];
    const int* edge_type       = (const int*)d_in[7];
    const int* user_edge_index = (const int*)d_in[8];
    const int* user_edge_type  = (const int*)d_in[9];
    const int* mat_row         = (const int*)d_in[10];
    const int* mat_col         = (const int*)d_in[11];

    int E  = in_sizes[7];
    int UE = in_sizes[9];
    int M  = in_sizes[10];

    float* out     = (float*)d_out;
    float* ent_out = out;
    float* usr_out = out + (size_t)N_ENT * D;

    int *p_ce, *p_cu, *p_cic, *p_cur, *p_oe, *p_ou, *p_oic, *p_our, *p_cursor;
    int *p_rkg, *p_ru, *p_rmc, *p_rmr, *p_be, *p_bu, *p_bic, *p_bur;
    float *p_iu, *p_ui;
    cudaGetSymbolAddress((void**)&p_ce,  g_cnt_e);
    cudaGetSymbolAddress((void**)&p_cu,  g_cnt_u);
    cudaGetSymbolAddress((void**)&p_cic, g_cnt_ic);
    cudaGetSymbolAddress((void**)&p_cur, g_cnt_ur);
    cudaGetSymbolAddress((void**)&p_oe,  g_off_e);
    cudaGetSymbolAddress((void**)&p_ou,  g_off_u);
    cudaGetSymbolAddress((void**)&p_oic, g_off_ic);
    cudaGetSymbolAddress((void**)&p_our, g_off_ur);
    cudaGetSymbolAddress((void**)&p_cursor, g_cursor);
    cudaGetSymbolAddress((void**)&p_rkg, g_rank_kg);
    cudaGetSymbolAddress((void**)&p_ru,  g_rank_u);
    cudaGetSymbolAddress((void**)&p_rmc, g_rank_mc);
    cudaGetSymbolAddress((void**)&p_rmr, g_rank_mr);
    cudaGetSymbolAddress((void**)&p_be,  g_bkt_e);
    cudaGetSymbolAddress((void**)&p_bu,  g_bkt_u);
    cudaGetSymbolAddress((void**)&p_bic, g_bkt_ic);
    cudaGetSymbolAddress((void**)&p_bur, g_bkt_ur);
    cudaGetSymbolAddress((void**)&p_iu,  g_iu);
    cudaGetSymbolAddress((void**)&p_ui,  g_ui);

    // 1) zero histograms + cursors
    zero_counts<<<512, 256>>>(p_ce, N_ENT, p_cu, N_UN, p_cic, N_ITEMS,
                              p_cur, N_USERS, p_cursor);

    // 2) histograms with per-edge rank
    hist_kernel<<<(E + 255) / 256, 256>>>(edge_index, p_ce, p_rkg, E);
    hist_kernel<<<(UE + 255) / 256, 256>>>(user_edge_index, p_cu, p_ru, UE);
    hist_mat_kernel<<<(M + 255) / 256, 256>>>(mat_row, mat_col,
                                              p_cur, p_rmr, p_cic, p_rmc, M);

    // 3) offsets
    offsets_kernel<<<(N_ENT   + 255) / 256, 256>>>(p_ce,  p_oe,  p_cursor + 0, N_ENT);
    offsets_kernel<<<(N_UN    + 255) / 256, 256>>>(p_cu,  p_ou,  p_cursor + 1, N_UN);
    offsets_kernel<<<(N_ITEMS + 255) / 256, 256>>>(p_cic, p_oic, p_cursor + 2, N_ITEMS);
    offsets_kernel<<<(N_USERS + 255) / 256, 256>>>(p_cur, p_our, p_cursor + 3, N_USERS);

    // 4) fill buckets
    fill_kernel<<<(E + 255) / 256, 256>>>(edge_index, edge_index + E, edge_type,
                                          p_oe, p_rkg, p_be, E);
    fill_kernel<<<(UE + 255) / 256, 256>>>(user_edge_index, user_edge_index + UE,
                                           user_edge_type, p_ou, p_ru, p_bu, UE);
    fill_mat_kernel<<<(M + 255) / 256, 256>>>(mat_row, mat_col,
                                              p_our, p_rmr, p_bur,
                                              p_oic, p_rmc, p_bic, M);

    // 5) gathers (write means directly; zero-degree rows write 0)
    gather_kernel<true><<<(N_ENT * 32 + 255) / 256, 256>>>(
        entity_emb, weight, p_be, p_oe, p_ce, ent_out, N_ENT);
    gather_kernel<true><<<(N_UN * 32 + 255) / 256, 256>>>(
        user_emb, weight, p_bu, p_ou, p_cu, usr_out, N_UN);
    gather_kernel<false><<<(N_ITEMS * 32 + 255) / 256, 256>>>(
        user_emb, weight, p_bic, p_oic, p_cic, p_iu, N_ITEMS);
    gather_kernel<false><<<(N_USERS * 32 + 255) / 256, 256>>>(
        entity_emb, weight, p_bur, p_our, p_cur, p_ui, N_USERS);

    // 6) gated fusion (in place over first N_ITEMS / N_USERS rows)
    fusion_kernel<<<888, 256>>>(ent_out, p_iu, gate1_w, gate2_w, ent_out, N_ITEMS);
    fusion_kernel<<<888, 256>>>(usr_out, p_ui, gate3_w, gate2_w, usr_out, N_USERS);
}